// round 16
// baseline (speedup 1.0000x reference)
#include <cuda_runtime.h>
#include <cstdint>

#define B_   4096
#define XD   128
#define YD   64
#define T_   200
#define LAT  100
#define CH   50
#define NBK  148
#define NT   1024
#define KP   232
#define NP   416
#define NKT  29
#define AS2  244     // A row stride (float2)
#define GST  426     // GX row stride (fp32)
#define O1S  108     // O1 row stride (float2)

// SMEM floats: 42636 = 170544 B (1 block/SM)
#define OFF_BIH 0
#define OFF_BHH 300
#define OFF_BL1 600
#define OFF_BL2 700
#define OFF_H   764        // [100][36] fp32 h ([j][r])
#define OFF_A   4364       // float2 [32][AS2]
#define OFF_YP  19980      // [64][33]
#define OFF_GX  22092      // [32][GST] fp32 (cols 304+ persist across G3 phase)
#define OFF_O1  35724      // float2 [32][O1S] (dedicated, no overlay)
#define SMEM_FLOATS 42636

__device__ float2 g_WB[KP * NP];
__device__ float2 g_W1[104 * 104];
__device__ float2 g_W2[104 * 64];

__device__ __forceinline__ float tf32_(float v) {
    unsigned r; asm("cvt.rna.tf32.f32 %0, %1;" : "=r"(r) : "f"(v));
    return __uint_as_float(r);
}
__device__ __forceinline__ float2 tfsplit(float v) {
    const float h = tf32_(v);
    return make_float2(h, tf32_(v - h));
}
__device__ __forceinline__ void mma8(float d[4], float a0, float a1, float a2, float a3,
                                     float b0, float b1) {
    asm("mma.sync.aligned.m16n8k8.row.col.f32.tf32.tf32.f32 "
        "{%0,%1,%2,%3}, {%4,%5,%6,%7}, {%8,%9}, {%0,%1,%2,%3};"
        : "+f"(d[0]), "+f"(d[1]), "+f"(d[2]), "+f"(d[3])
        : "r"(__float_as_uint(a0)), "r"(__float_as_uint(a1)),
          "r"(__float_as_uint(a2)), "r"(__float_as_uint(a3)),
          "r"(__float_as_uint(b0)), "r"(__float_as_uint(b1)));
}
__device__ __forceinline__ void mma3(float d[4], const float2 F[4], float2 b0, float2 b1) {
    mma8(d, F[0].x, F[1].x, F[2].x, F[3].x, b0.x, b1.x);
    mma8(d, F[0].x, F[1].x, F[2].x, F[3].x, b0.y, b1.y);
    mma8(d, F[0].y, F[1].y, F[2].y, F[3].y, b0.x, b1.x);
}
__device__ __forceinline__ void ldfrag(float2 F[8], const float2* base, int st, int g, int col) {
    F[0] = base[g * st + col];            F[1] = base[(g + 8) * st + col];
    F[2] = base[g * st + col + 4];        F[3] = base[(g + 8) * st + col + 4];
    F[4] = base[(g + 16) * st + col];     F[5] = base[(g + 24) * st + col];
    F[6] = base[(g + 16) * st + col + 4]; F[7] = base[(g + 24) * st + col + 4];
}
__device__ __forceinline__ void storeD(float* smp, int g, int cc, int n0, int gst,
                                       const float D[8]) {
#pragma unroll
    for (int i = 0; i < 8; i += 2) {
        const int row = g + (i >> 2) * 16 + ((i >> 1) & 1) * 8;
        *(float2*)&smp[row * gst + n0 + 2 * cc] = make_float2(D[i], D[i + 1]);
    }
}
__device__ __forceinline__ float rcp_(float x) {
    float r; asm("rcp.approx.f32 %0, %1;" : "=f"(r) : "f"(x)); return r;
}
__device__ __forceinline__ void rcp4(const float d[4], float inv[4]) {
    const float p1 = d[0] * d[1], p2 = p1 * d[2], p3 = p2 * d[3];
    const float q3 = rcp_(p3);
    inv[3] = q3 * p2;
    const float q2 = q3 * d[3];
    inv[2] = q2 * p1;
    const float q1 = q2 * d[2];
    inv[1] = q1 * d[0];
    inv[0] = q1 * d[1];
}
__device__ __forceinline__ float fsig(float x) {
    return __fdividef(1.0f, 1.0f + __expf(-x));
}
__device__ __forceinline__ float ftanh_(float x) {
    float e = __expf(2.0f * x);
    return 1.0f - __fdividef(2.0f, e + 1.0f);
}

__global__ void prep_kernel(const float* __restrict__ Wih, const float* __restrict__ Whh,
                            const float* __restrict__ Wl1, const float* __restrict__ Wl2)
{
    const int total = KP * NP + 104 * 104 + 104 * 64;
    for (int i = blockIdx.x * blockDim.x + threadIdx.x; i < total;
         i += gridDim.x * blockDim.x) {
        float v = 0.f;
        if (i < KP * NP) {
            const int k = i / NP, n = i % NP;
            if (n < 200) {
                if (k < XD) v = Wih[k * 300 + n];
                else if (k < 228) v = Whh[(k - XD) * 300 + n];
            } else if (n < 300) {
                if (k < XD) v = Wih[k * 300 + n];
            } else if (n >= 304 && n < 404) {
                if (k >= XD && k < 228) v = Whh[(k - XD) * 300 + (n - 104)];
            }
            g_WB[i] = tfsplit(v);
        } else if (i < KP * NP + 104 * 104) {
            const int e = i - KP * NP, k = e / 104, n = e % 104;
            if (k < 100 && n < 100) v = Wl1[k * 100 + n];
            g_W1[e] = tfsplit(v);
        } else {
            const int e = i - KP * NP - 104 * 104, k = e / 64, n = e % 64;
            if (k < 100) v = Wl2[k * 64 + n];
            g_W2[e] = tfsplit(v);
        }
    }
}

extern "C" __global__ void __launch_bounds__(NT, 1) gru_kernel(
    const float* __restrict__ x, const float* __restrict__ y, const void* __restrict__ ymask,
    const float* __restrict__ Wmu1, const float* __restrict__ bmu1,
    const float* __restrict__ Wmu2, const float* __restrict__ bmu2,
    const float* __restrict__ bih, const float* __restrict__ bhh,
    const float* __restrict__ bl1, const float* __restrict__ bl2,
    const float* __restrict__ Wc1, const float* __restrict__ bc1,
    const float* __restrict__ Wc2, const float* __restrict__ bc2,
    float* __restrict__ out, int has_cls)
{
    extern __shared__ float sm[];
    float2* Af  = (float2*)(sm + OFF_A);
    float2* O1f = (float2*)(sm + OFF_O1);
    const int tid  = threadIdx.x;
    const int lane = tid & 31;
    const int wid  = tid >> 5;        // 0..31
    const int g    = lane >> 2;
    const int cc   = lane & 3;
    const int b0   = (B_ * blockIdx.x) / NBK;
    const int nr   = (B_ * (blockIdx.x + 1)) / NBK - b0;   // 27 or 28
    const int j0   = lane * 4;

    // ---- stage biases; zero YP + A pad cols ----
    for (int i = tid; i < 300; i += NT) {
        sm[OFF_BIH + i] = (i < 200) ? bih[i] + bhh[i] : bih[i];
        sm[OFF_BHH + i] = bhh[i];
    }
    for (int i = tid; i < LAT; i += NT) sm[OFF_BL1 + i] = bl1[i];
    for (int i = tid; i < YD;  i += NT) sm[OFF_BL2 + i] = bl2[i];
    for (int i = tid; i < YD * 33; i += NT) sm[OFF_YP + i] = 0.f;
    if (tid < 128) Af[(tid >> 2) * AS2 + 228 + (tid & 3)] = make_float2(0.f, 0.f);

    // ---- mask dtype detection ----
    const unsigned word = ((const unsigned*)ymask)[tid & 255];
    const int big = __syncthreads_or((word & 0xFEFEFEFEu) != 0u);
    const int odd = __syncthreads_or((word & 0xFFFFFF00u) != 0u);
    const int mode = big ? 2 : (odd ? 0 : 1);

    // ---- stage x fp32 into GX scratch [32][132] ----
    float* Xs = sm + OFF_GX;
    for (int i = tid; i < 32 * XD; i += NT) {
        const int r = i & 31, k = i >> 5;
        Xs[r * 132 + k] = (r < nr) ? __ldg(&x[(size_t)(b0 + r) * XD + k]) : 0.f;
    }
    __syncthreads();

    // ---- h0 encoder (FFMA, once): warp = row ----
    float* tmp = sm + OFF_GX + 4224;
    if (lane < 25) {
        float a[4] = {0, 0, 0, 0};
        for (int k = 0; k < XD; k++) {
            const float xv = Xs[wid * 132 + k];
            const float4 w = __ldg((const float4*)&Wmu1[k * LAT + j0]);
            a[0] = fmaf(xv, w.x, a[0]); a[1] = fmaf(xv, w.y, a[1]);
            a[2] = fmaf(xv, w.z, a[2]); a[3] = fmaf(xv, w.w, a[3]);
        }
        const float4 bb = __ldg((const float4*)&bmu1[j0]);
        tmp[(j0 + 0) * 36 + wid] = ftanh_(a[0] + bb.x);
        tmp[(j0 + 1) * 36 + wid] = ftanh_(a[1] + bb.y);
        tmp[(j0 + 2) * 36 + wid] = ftanh_(a[2] + bb.z);
        tmp[(j0 + 3) * 36 + wid] = ftanh_(a[3] + bb.w);
    }
    __syncthreads();
    if (lane < 25) {
        float a[4] = {0, 0, 0, 0};
        for (int k = 0; k < LAT; k++) {
            const float tv = tmp[k * 36 + wid];
            const float4 w = __ldg((const float4*)&Wmu2[k * LAT + j0]);
            a[0] = fmaf(tv, w.x, a[0]); a[1] = fmaf(tv, w.y, a[1]);
            a[2] = fmaf(tv, w.z, a[2]); a[3] = fmaf(tv, w.w, a[3]);
        }
        const float4 bb = __ldg((const float4*)&bmu2[j0]);
        const float hv[4] = {a[0] + bb.x, a[1] + bb.y, a[2] + bb.z, a[3] + bb.w};
#pragma unroll
        for (int i = 0; i < 4; i++) {
            sm[OFF_H + (j0 + i) * 36 + wid] = hv[i];
            Af[wid * AS2 + 128 + j0 + i] = tfsplit(hv[i]);
        }
    }

    // ---- y/mask preload ----
    float yv[2], mfv[2];
    auto preload = [&](int t) {
#pragma unroll
        for (int i = 0; i < 2; i++) {
            const int e = tid + NT * i;
            const int r = e & 31, d = e >> 5;
            if (r < nr) {
                const size_t off = (size_t)(b0 + r) * (YD * T_) + (size_t)d * T_ + t;
                yv[i] = __ldg(&y[off]);
                float m;
                if (mode == 0)      m = (((const unsigned char*)ymask)[off] != 0) ? 1.f : 0.f;
                else if (mode == 1) m = (((const int*)ymask)[off] != 0) ? 1.f : 0.f;
                else                m = (((const float*)ymask)[off] != 0.f) ? 1.f : 0.f;
                mfv[i] = m;
            } else { yv[i] = 0.f; mfv[i] = 0.f; }
        }
    };
    preload(0);
    __syncthreads();

    // ---- pre-loop: nh tiles for t=0 (reads Af h-cols, writes GX cols 304+) ----
    auto nh_tiles = [&]() {
        if (wid >= 13 && wid < 26) {
            const int n0 = 304 + 8 * (wid - 13);
            float D[8];
#pragma unroll
            for (int i = 0; i < 8; i++) D[i] = 0.f;
            for (int kt = 16; kt < NKT; kt++) {
                const int kk = kt * 8;
                float2 F[8];
                ldfrag(F, Af, AS2, g, kk + cc);
                const float2 b0v = __ldg(&g_WB[(kk + cc) * NP + n0 + g]);
                const float2 b1v = __ldg(&g_WB[(kk + cc + 4) * NP + n0 + g]);
                mma3(&D[0], F, b0v, b1v);
                mma3(&D[4], F + 4, b0v, b1v);
            }
            storeD(sm + OFF_GX, g, cc, n0, GST, D);
        }
    };
    nh_tiles();
    __syncthreads();

    // ================= main recurrence (5 barriers/step) =================
    for (int t = 0; t < T_; ++t) {
        // -- teacher forcing -> A cols 0..127 --
#pragma unroll
        for (int i = 0; i < 2; i++) {
            const int e = tid + NT * i;
            const int r = e & 31, d = e >> 5;
            const float m  = mfv[i];
            const float yp = sm[OFF_YP + d * 33 + r];
            const float yin = (m != 0.f) ? yv[i] : yp;
            Af[r * AS2 + 2 * d]     = tfsplit(yin);
            Af[r * AS2 + 2 * d + 1] = make_float2(m, 0.f);
        }
        if (t + 1 < T_) preload(t + 1);
        __syncthreads();

        // -- P1 (tensor): r/z + nx tiles only (nh precomputed) --
        if (wid < 6) {
            // two r/z tiles, F reused across both
            const int n0a = 16 * wid, n0b = n0a + 8;
            float Da[8], Db[8];
#pragma unroll
            for (int i = 0; i < 8; i++) { Da[i] = 0.f; Db[i] = 0.f; }
            for (int kt = 0; kt < NKT; kt++) {
                const int kk = kt * 8;
                float2 F[8];
                ldfrag(F, Af, AS2, g, kk + cc);
                const float2 ba0 = __ldg(&g_WB[(kk + cc) * NP + n0a + g]);
                const float2 ba1 = __ldg(&g_WB[(kk + cc + 4) * NP + n0a + g]);
                mma3(&Da[0], F, ba0, ba1);
                mma3(&Da[4], F + 4, ba0, ba1);
                const float2 bb0 = __ldg(&g_WB[(kk + cc) * NP + n0b + g]);
                const float2 bb1 = __ldg(&g_WB[(kk + cc + 4) * NP + n0b + g]);
                mma3(&Db[0], F, bb0, bb1);
                mma3(&Db[4], F + 4, bb0, bb1);
            }
            storeD(sm + OFF_GX, g, cc, n0a, GST, Da);
            storeD(sm + OFF_GX, g, cc, n0b, GST, Db);
        } else if (wid < 19) {
            // one r/z tile
            const int n0 = 96 + 8 * (wid - 6);
            float D[8];
#pragma unroll
            for (int i = 0; i < 8; i++) D[i] = 0.f;
            for (int kt = 0; kt < NKT; kt++) {
                const int kk = kt * 8;
                float2 F[8];
                ldfrag(F, Af, AS2, g, kk + cc);
                const float2 b0v = __ldg(&g_WB[(kk + cc) * NP + n0 + g]);
                const float2 b1v = __ldg(&g_WB[(kk + cc + 4) * NP + n0 + g]);
                mma3(&D[0], F, b0v, b1v);
                mma3(&D[4], F + 4, b0v, b1v);
            }
            storeD(sm + OFF_GX, g, cc, n0, GST, D);
        } else {
            // one nx tile (kt 0..16)
            const int n0 = 200 + 8 * (wid - 19);
            float D[8];
#pragma unroll
            for (int i = 0; i < 8; i++) D[i] = 0.f;
            for (int kt = 0; kt < 16; kt++) {
                const int kk = kt * 8;
                float2 F[8];
                ldfrag(F, Af, AS2, g, kk + cc);
                const float2 b0v = __ldg(&g_WB[(kk + cc) * NP + n0 + g]);
                const float2 b1v = __ldg(&g_WB[(kk + cc + 4) * NP + n0 + g]);
                mma3(&D[0], F, b0v, b1v);
                mma3(&D[4], F + 4, b0v, b1v);
            }
            storeD(sm + OFF_GX, g, cc, n0, GST, D);
        }
        __syncthreads();

        // -- gates (batched RCP): 800 items, 1/thread --
        if (tid < 800) {
            const int j  = tid % 100;
            const int r0 = (tid / 100) << 2;
            float gr[4], gz[4], gxv[4], gh[4];
#pragma unroll
            for (int i = 0; i < 4; i++) {
                const float* GX = sm + OFF_GX + (r0 + i) * GST;
                gr[i]  = GX[j]       + sm[OFF_BIH + j];
                gz[i]  = GX[100 + j] + sm[OFF_BIH + 100 + j];
                gxv[i] = GX[200 + j] + sm[OFF_BIH + 200 + j];
                gh[i]  = GX[304 + j] + sm[OFF_BHH + 200 + j];
            }
            float dr[4], dz[4], rg[4], zg[4];
#pragma unroll
            for (int i = 0; i < 4; i++) {
                dr[i] = 1.f + __expf(-fminf(fmaxf(gr[i], -15.f), 15.f));
                dz[i] = 1.f + __expf(-fminf(fmaxf(gz[i], -15.f), 15.f));
            }
            rcp4(dr, rg);
            rcp4(dz, zg);
            float dn[4], iv[4];
#pragma unroll
            for (int i = 0; i < 4; i++) {
                float u = gxv[i] + rg[i] * gh[i];
                u = fminf(fmaxf(u, -10.f), 10.f);
                dn[i] = __expf(2.f * u) + 1.f;
            }
            rcp4(dn, iv);
#pragma unroll
            for (int i = 0; i < 4; i++) {
                const float n  = 1.f - 2.f * iv[i];
                const float ho = sm[OFF_H + j * 36 + r0 + i];
                const float hn = (1.f - zg[i]) * n + zg[i] * ho;
                sm[OFF_H + j * 36 + r0 + i] = hn;
                Af[(r0 + i) * AS2 + 128 + j] = tfsplit(hn);
            }
        }
        __syncthreads();

        // -- G3 (warps 0-12) + next-step nh tiles (warps 13-25) in parallel --
        if (wid < 13) {
            const int n0 = wid * 8;
            float D[8];
#pragma unroll
            for (int i = 0; i < 8; i++) D[i] = 0.f;
            for (int kt = 0; kt < 13; kt++) {
                const int kk = kt * 8;
                float2 F[8];
                ldfrag(F, Af, AS2, g, 128 + kk + cc);
                const float2 b0v = __ldg(&g_W1[(kk + cc) * 104 + n0 + g]);
                const float2 b1v = __ldg(&g_W1[(kk + cc + 4) * 104 + n0 + g]);
                mma3(&D[0], F, b0v, b1v);
                mma3(&D[4], F + 4, b0v, b1v);
            }
            float dv[8], iv[8];
#pragma unroll
            for (int i = 0; i < 8; i++) {
                const int col = n0 + 2 * cc + (i & 1);
                const float bb = (col < 100) ? sm[OFF_BL1 + col] : 0.f;
                const float u = fminf(fmaxf(D[i] + bb, -10.f), 10.f);
                dv[i] = __expf(2.f * u) + 1.f;
            }
            rcp4(dv, iv);
            rcp4(dv + 4, iv + 4);
#pragma unroll
            for (int i = 0; i < 8; i++) {
                const int row = g + (i >> 2) * 16 + ((i >> 1) & 1) * 8;
                const int col = n0 + 2 * cc + (i & 1);
                O1f[row * O1S + col] = tfsplit(1.f - 2.f * iv[i]);
            }
        } else if (t + 1 < T_) {
            nh_tiles();           // writes GX cols 304+ for step t+1
        }
        __syncthreads();

        // -- G4 (tensor): out_t = o1 @ Wl2 + bl2; writes out + YP --
        if (wid < 8) {
            const int n0 = wid * 8;
            float D[8];
#pragma unroll
            for (int i = 0; i < 8; i++) D[i] = 0.f;
            for (int kt = 0; kt < 13; kt++) {
                const int kk = kt * 8;
                float2 F[8];
                ldfrag(F, O1f, O1S, g, kk + cc);
                const float2 b0v = __ldg(&g_W2[(kk + cc) * 64 + n0 + g]);
                const float2 b1v = __ldg(&g_W2[(kk + cc + 4) * 64 + n0 + g]);
                mma3(&D[0], F, b0v, b1v);
                mma3(&D[4], F + 4, b0v, b1v);
            }
#pragma unroll
            for (int i = 0; i < 8; i++) {
                const int row = g + (i >> 2) * 16 + ((i >> 1) & 1) * 8;
                const int col = n0 + 2 * cc + (i & 1);
                const float v = D[i] + sm[OFF_BL2 + col];
                if (row < nr)
                    out[(size_t)(b0 + row) * (YD * T_) + (size_t)col * T_ + t] = v;
                sm[OFF_YP + col * 33 + row] = v;
            }
        }
        __syncthreads();
    }

    // ---- classifier ----
    if (has_cls) {
        float* scr = sm + OFF_GX;
        __syncthreads();
        for (int idx = tid; idx < 32 * CH; idx += NT) {
            const int r = idx & 31, c = idx >> 5;
            float acc = __ldg(&bc1[c]);
            for (int k = 0; k < LAT; k++)
                acc = fmaf(sm[OFF_H + k * 36 + r], __ldg(&Wc1[k * CH + c]), acc);
            scr[c * 36 + r] = fmaxf(acc, 0.f);
        }
        __syncthreads();
        if (tid < nr) {
            float acc = __ldg(&bc2[0]);
            for (int c = 0; c < CH; c++)
                acc = fmaf(scr[c * 36 + tid], __ldg(&Wc2[c]), acc);
            out[(size_t)B_ * YD * T_ + b0 + tid] = fsig(acc);
        }
    }
}

extern "C" void kernel_launch(void* const* d_in, const int* in_sizes, int n_in,
                              void* d_out, int out_size)
{
    cudaFuncSetAttribute(gru_kernel, cudaFuncAttributeMaxDynamicSharedMemorySize,
                         SMEM_FLOATS * (int)sizeof(float));
    prep_kernel<<<128, 256>>>((const float*)d_in[11], (const float*)d_in[13],
                              (const float*)d_in[15], (const float*)d_in[17]);
    const int has_cls = (out_size > B_ * YD * T_) ? 1 : 0;
    gru_kernel<<<NBK, NT, SMEM_FLOATS * sizeof(float)>>>(
        (const float*)d_in[0],   // x
        (const float*)d_in[1],   // y
        d_in[2],                 // y_mask (dtype auto-detected)
        (const float*)d_in[3],  (const float*)d_in[4],   // Wmu1, bmu1
        (const float*)d_in[5],  (const float*)d_in[6],   // Wmu2, bmu2
        (const float*)d_in[12], (const float*)d_in[14],  // bih, bhh
        (const float*)d_in[16], (const float*)d_in[18],  // bl1, bl2
        (const float*)d_in[19], (const float*)d_in[20],  // Wc1, bc1
        (const float*)d_in[21], (const float*)d_in[22],  // Wc2, bc2
        (float*)d_out, has_cls);
}

// round 17
// speedup vs baseline: 1.0009x; 1.0009x over previous
#include <cuda_runtime.h>
#include <cstdint>

#define B_   4096
#define XD   128
#define YD   64
#define T_   200
#define LAT  100
#define CH   50
#define NBK  148
#define NT   1024
#define KP   232
#define NP   416
#define NKT  29
#define AS2  244     // A row stride (float2)
#define GST  426     // GX row stride (fp32)
#define O1S  108     // O1 row stride (float2)

// SMEM floats: 42636 = 170544 B (1 block/SM)
#define OFF_BIH 0
#define OFF_BHH 300
#define OFF_BL1 600
#define OFF_BL2 700
#define OFF_H   764        // [100][36] fp32 h ([j][r])
#define OFF_A   4364       // float2 [32][AS2]
#define OFF_YP  19980      // [64][33]
#define OFF_GX  22092      // [32][GST] fp32 (cols 304+ persist across G3 phase)
#define OFF_O1  35724      // float2 [32][O1S] (dedicated, no overlay)
#define SMEM_FLOATS 42636

__device__ float2 g_WB[KP * NP];
__device__ float2 g_W1[104 * 104];
__device__ float2 g_W2[104 * 64];

__device__ __forceinline__ float tf32_(float v) {
    unsigned r; asm("cvt.rna.tf32.f32 %0, %1;" : "=r"(r) : "f"(v));
    return __uint_as_float(r);
}
__device__ __forceinline__ float2 tfsplit(float v) {
    const float h = tf32_(v);
    return make_float2(h, tf32_(v - h));
}
__device__ __forceinline__ void mma8(float d[4], float a0, float a1, float a2, float a3,
                                     float b0, float b1) {
    asm("mma.sync.aligned.m16n8k8.row.col.f32.tf32.tf32.f32 "
        "{%0,%1,%2,%3}, {%4,%5,%6,%7}, {%8,%9}, {%0,%1,%2,%3};"
        : "+f"(d[0]), "+f"(d[1]), "+f"(d[2]), "+f"(d[3])
        : "r"(__float_as_uint(a0)), "r"(__float_as_uint(a1)),
          "r"(__float_as_uint(a2)), "r"(__float_as_uint(a3)),
          "r"(__float_as_uint(b0)), "r"(__float_as_uint(b1)));
}
__device__ __forceinline__ void mma3(float d[4], const float2 F[4], float2 b0, float2 b1) {
    mma8(d, F[0].x, F[1].x, F[2].x, F[3].x, b0.x, b1.x);
    mma8(d, F[0].x, F[1].x, F[2].x, F[3].x, b0.y, b1.y);
    mma8(d, F[0].y, F[1].y, F[2].y, F[3].y, b0.x, b1.x);
}
__device__ __forceinline__ void ldfrag(float2 F[8], const float2* base, int st, int g, int col) {
    F[0] = base[g * st + col];            F[1] = base[(g + 8) * st + col];
    F[2] = base[g * st + col + 4];        F[3] = base[(g + 8) * st + col + 4];
    F[4] = base[(g + 16) * st + col];     F[5] = base[(g + 24) * st + col];
    F[6] = base[(g + 16) * st + col + 4]; F[7] = base[(g + 24) * st + col + 4];
}
__device__ __forceinline__ void storeD(float* smp, int g, int cc, int n0, int gst,
                                       const float D[8]) {
#pragma unroll
    for (int i = 0; i < 8; i += 2) {
        const int row = g + (i >> 2) * 16 + ((i >> 1) & 1) * 8;
        *(float2*)&smp[row * gst + n0 + 2 * cc] = make_float2(D[i], D[i + 1]);
    }
}
__device__ __forceinline__ float rcp_(float x) {
    float r; asm("rcp.approx.f32 %0, %1;" : "=f"(r) : "f"(x)); return r;
}
__device__ __forceinline__ void rcp4(const float d[4], float inv[4]) {
    const float p1 = d[0] * d[1], p2 = p1 * d[2], p3 = p2 * d[3];
    const float q3 = rcp_(p3);
    inv[3] = q3 * p2;
    const float q2 = q3 * d[3];
    inv[2] = q2 * p1;
    const float q1 = q2 * d[2];
    inv[1] = q1 * d[0];
    inv[0] = q1 * d[1];
}
__device__ __forceinline__ float fsig(float x) {
    return __fdividef(1.0f, 1.0f + __expf(-x));
}
__device__ __forceinline__ float ftanh_(float x) {
    float e = __expf(2.0f * x);
    return 1.0f - __fdividef(2.0f, e + 1.0f);
}

__global__ void prep_kernel(const float* __restrict__ Wih, const float* __restrict__ Whh,
                            const float* __restrict__ Wl1, const float* __restrict__ Wl2)
{
    const int total = KP * NP + 104 * 104 + 104 * 64;
    for (int i = blockIdx.x * blockDim.x + threadIdx.x; i < total;
         i += gridDim.x * blockDim.x) {
        float v = 0.f;
        if (i < KP * NP) {
            const int k = i / NP, n = i % NP;
            if (n < 200) {
                if (k < XD) v = Wih[k * 300 + n];
                else if (k < 228) v = Whh[(k - XD) * 300 + n];
            } else if (n < 300) {
                if (k < XD) v = Wih[k * 300 + n];
            } else if (n >= 304 && n < 404) {
                if (k >= XD && k < 228) v = Whh[(k - XD) * 300 + (n - 104)];
            }
            g_WB[i] = tfsplit(v);
        } else if (i < KP * NP + 104 * 104) {
            const int e = i - KP * NP, k = e / 104, n = e % 104;
            if (k < 100 && n < 100) v = Wl1[k * 100 + n];
            g_W1[e] = tfsplit(v);
        } else {
            const int e = i - KP * NP - 104 * 104, k = e / 64, n = e % 64;
            if (k < 100) v = Wl2[k * 64 + n];
            g_W2[e] = tfsplit(v);
        }
    }
}

extern "C" __global__ void __launch_bounds__(NT, 1) gru_kernel(
    const float* __restrict__ x, const float* __restrict__ y, const void* __restrict__ ymask,
    const float* __restrict__ Wmu1, const float* __restrict__ bmu1,
    const float* __restrict__ Wmu2, const float* __restrict__ bmu2,
    const float* __restrict__ bih, const float* __restrict__ bhh,
    const float* __restrict__ bl1, const float* __restrict__ bl2,
    const float* __restrict__ Wc1, const float* __restrict__ bc1,
    const float* __restrict__ Wc2, const float* __restrict__ bc2,
    float* __restrict__ out, int has_cls)
{
    extern __shared__ float sm[];
    float2* Af  = (float2*)(sm + OFF_A);
    float2* O1f = (float2*)(sm + OFF_O1);
    const int tid  = threadIdx.x;
    const int lane = tid & 31;
    const int wid  = tid >> 5;        // 0..31
    const int g    = lane >> 2;
    const int cc   = lane & 3;
    const int b0   = (B_ * blockIdx.x) / NBK;
    const int nr   = (B_ * (blockIdx.x + 1)) / NBK - b0;   // 27 or 28
    const int j0   = lane * 4;

    // ---- stage biases; zero YP + A pad cols ----
    for (int i = tid; i < 300; i += NT) {
        sm[OFF_BIH + i] = (i < 200) ? bih[i] + bhh[i] : bih[i];
        sm[OFF_BHH + i] = bhh[i];
    }
    for (int i = tid; i < LAT; i += NT) sm[OFF_BL1 + i] = bl1[i];
    for (int i = tid; i < YD;  i += NT) sm[OFF_BL2 + i] = bl2[i];
    for (int i = tid; i < YD * 33; i += NT) sm[OFF_YP + i] = 0.f;
    if (tid < 128) Af[(tid >> 2) * AS2 + 228 + (tid & 3)] = make_float2(0.f, 0.f);

    // ---- mask dtype detection ----
    const unsigned word = ((const unsigned*)ymask)[tid & 255];
    const int big = __syncthreads_or((word & 0xFEFEFEFEu) != 0u);
    const int odd = __syncthreads_or((word & 0xFFFFFF00u) != 0u);
    const int mode = big ? 2 : (odd ? 0 : 1);

    // ---- stage x fp32 into GX scratch [32][132] ----
    float* Xs = sm + OFF_GX;
    for (int i = tid; i < 32 * XD; i += NT) {
        const int r = i & 31, k = i >> 5;
        Xs[r * 132 + k] = (r < nr) ? __ldg(&x[(size_t)(b0 + r) * XD + k]) : 0.f;
    }
    __syncthreads();

    // ---- h0 encoder (FFMA, once): warp = row ----
    float* tmp = sm + OFF_GX + 4224;
    if (lane < 25) {
        float a[4] = {0, 0, 0, 0};
        for (int k = 0; k < XD; k++) {
            const float xv = Xs[wid * 132 + k];
            const float4 w = __ldg((const float4*)&Wmu1[k * LAT + j0]);
            a[0] = fmaf(xv, w.x, a[0]); a[1] = fmaf(xv, w.y, a[1]);
            a[2] = fmaf(xv, w.z, a[2]); a[3] = fmaf(xv, w.w, a[3]);
        }
        const float4 bb = __ldg((const float4*)&bmu1[j0]);
        tmp[(j0 + 0) * 36 + wid] = ftanh_(a[0] + bb.x);
        tmp[(j0 + 1) * 36 + wid] = ftanh_(a[1] + bb.y);
        tmp[(j0 + 2) * 36 + wid] = ftanh_(a[2] + bb.z);
        tmp[(j0 + 3) * 36 + wid] = ftanh_(a[3] + bb.w);
    }
    __syncthreads();
    if (lane < 25) {
        float a[4] = {0, 0, 0, 0};
        for (int k = 0; k < LAT; k++) {
            const float tv = tmp[k * 36 + wid];
            const float4 w = __ldg((const float4*)&Wmu2[k * LAT + j0]);
            a[0] = fmaf(tv, w.x, a[0]); a[1] = fmaf(tv, w.y, a[1]);
            a[2] = fmaf(tv, w.z, a[2]); a[3] = fmaf(tv, w.w, a[3]);
        }
        const float4 bb = __ldg((const float4*)&bmu2[j0]);
        const float hv[4] = {a[0] + bb.x, a[1] + bb.y, a[2] + bb.z, a[3] + bb.w};
#pragma unroll
        for (int i = 0; i < 4; i++) {
            sm[OFF_H + (j0 + i) * 36 + wid] = hv[i];
            Af[wid * AS2 + 128 + j0 + i] = tfsplit(hv[i]);
        }
    }

    // ---- y/mask preload ----
    float yv[2], mfv[2];
    auto preload = [&](int t) {
#pragma unroll
        for (int i = 0; i < 2; i++) {
            const int e = tid + NT * i;
            const int r = e & 31, d = e >> 5;
            if (r < nr) {
                const size_t off = (size_t)(b0 + r) * (YD * T_) + (size_t)d * T_ + t;
                yv[i] = __ldg(&y[off]);
                float m;
                if (mode == 0)      m = (((const unsigned char*)ymask)[off] != 0) ? 1.f : 0.f;
                else if (mode == 1) m = (((const int*)ymask)[off] != 0) ? 1.f : 0.f;
                else                m = (((const float*)ymask)[off] != 0.f) ? 1.f : 0.f;
                mfv[i] = m;
            } else { yv[i] = 0.f; mfv[i] = 0.f; }
        }
    };
    preload(0);
    __syncthreads();

    // ---- pre-loop: nh tiles for t=0 (reads Af h-cols, writes GX cols 304+) ----
    auto nh_tiles = [&]() {
        if (wid >= 13 && wid < 26) {
            const int n0 = 304 + 8 * (wid - 13);
            float D[8];
#pragma unroll
            for (int i = 0; i < 8; i++) D[i] = 0.f;
            for (int kt = 16; kt < NKT; kt++) {
                const int kk = kt * 8;
                float2 F[8];
                ldfrag(F, Af, AS2, g, kk + cc);
                const float2 b0v = __ldg(&g_WB[(kk + cc) * NP + n0 + g]);
                const float2 b1v = __ldg(&g_WB[(kk + cc + 4) * NP + n0 + g]);
                mma3(&D[0], F, b0v, b1v);
                mma3(&D[4], F + 4, b0v, b1v);
            }
            storeD(sm + OFF_GX, g, cc, n0, GST, D);
        }
    };
    nh_tiles();
    __syncthreads();

    // ================= main recurrence (5 barriers/step) =================
    for (int t = 0; t < T_; ++t) {
        // -- teacher forcing -> A cols 0..127 --
#pragma unroll
        for (int i = 0; i < 2; i++) {
            const int e = tid + NT * i;
            const int r = e & 31, d = e >> 5;
            const float m  = mfv[i];
            const float yp = sm[OFF_YP + d * 33 + r];
            const float yin = (m != 0.f) ? yv[i] : yp;
            Af[r * AS2 + 2 * d]     = tfsplit(yin);
            Af[r * AS2 + 2 * d + 1] = make_float2(m, 0.f);
        }
        if (t + 1 < T_) preload(t + 1);
        __syncthreads();

        // -- P1 (tensor): r/z + nx tiles only (nh precomputed) --
        if (wid < 6) {
            // two r/z tiles, F reused across both
            const int n0a = 16 * wid, n0b = n0a + 8;
            float Da[8], Db[8];
#pragma unroll
            for (int i = 0; i < 8; i++) { Da[i] = 0.f; Db[i] = 0.f; }
            for (int kt = 0; kt < NKT; kt++) {
                const int kk = kt * 8;
                float2 F[8];
                ldfrag(F, Af, AS2, g, kk + cc);
                const float2 ba0 = __ldg(&g_WB[(kk + cc) * NP + n0a + g]);
                const float2 ba1 = __ldg(&g_WB[(kk + cc + 4) * NP + n0a + g]);
                mma3(&Da[0], F, ba0, ba1);
                mma3(&Da[4], F + 4, ba0, ba1);
                const float2 bb0 = __ldg(&g_WB[(kk + cc) * NP + n0b + g]);
                const float2 bb1 = __ldg(&g_WB[(kk + cc + 4) * NP + n0b + g]);
                mma3(&Db[0], F, bb0, bb1);
                mma3(&Db[4], F + 4, bb0, bb1);
            }
            storeD(sm + OFF_GX, g, cc, n0a, GST, Da);
            storeD(sm + OFF_GX, g, cc, n0b, GST, Db);
        } else if (wid < 19) {
            // one r/z tile
            const int n0 = 96 + 8 * (wid - 6);
            float D[8];
#pragma unroll
            for (int i = 0; i < 8; i++) D[i] = 0.f;
            for (int kt = 0; kt < NKT; kt++) {
                const int kk = kt * 8;
                float2 F[8];
                ldfrag(F, Af, AS2, g, kk + cc);
                const float2 b0v = __ldg(&g_WB[(kk + cc) * NP + n0 + g]);
                const float2 b1v = __ldg(&g_WB[(kk + cc + 4) * NP + n0 + g]);
                mma3(&D[0], F, b0v, b1v);
                mma3(&D[4], F + 4, b0v, b1v);
            }
            storeD(sm + OFF_GX, g, cc, n0, GST, D);
        } else {
            // one nx tile (kt 0..16)
            const int n0 = 200 + 8 * (wid - 19);
            float D[8];
#pragma unroll
            for (int i = 0; i < 8; i++) D[i] = 0.f;
            for (int kt = 0; kt < 16; kt++) {
                const int kk = kt * 8;
                float2 F[8];
                ldfrag(F, Af, AS2, g, kk + cc);
                const float2 b0v = __ldg(&g_WB[(kk + cc) * NP + n0 + g]);
                const float2 b1v = __ldg(&g_WB[(kk + cc + 4) * NP + n0 + g]);
                mma3(&D[0], F, b0v, b1v);
                mma3(&D[4], F + 4, b0v, b1v);
            }
            storeD(sm + OFF_GX, g, cc, n0, GST, D);
        }
        __syncthreads();

        // -- gates (batched RCP): 800 items, 1/thread --
        if (tid < 800) {
            const int j  = tid % 100;
            const int r0 = (tid / 100) << 2;
            float gr[4], gz[4], gxv[4], gh[4];
#pragma unroll
            for (int i = 0; i < 4; i++) {
                const float* GX = sm + OFF_GX + (r0 + i) * GST;
                gr[i]  = GX[j]       + sm[OFF_BIH + j];
                gz[i]  = GX[100 + j] + sm[OFF_BIH + 100 + j];
                gxv[i] = GX[200 + j] + sm[OFF_BIH + 200 + j];
                gh[i]  = GX[304 + j] + sm[OFF_BHH + 200 + j];
            }
            float dr[4], dz[4], rg[4], zg[4];
#pragma unroll
            for (int i = 0; i < 4; i++) {
                dr[i] = 1.f + __expf(-fminf(fmaxf(gr[i], -15.f), 15.f));
                dz[i] = 1.f + __expf(-fminf(fmaxf(gz[i], -15.f), 15.f));
            }
            rcp4(dr, rg);
            rcp4(dz, zg);
            float dn[4], iv[4];
#pragma unroll
            for (int i = 0; i < 4; i++) {
                float u = gxv[i] + rg[i] * gh[i];
                u = fminf(fmaxf(u, -10.f), 10.f);
                dn[i] = __expf(2.f * u) + 1.f;
            }
            rcp4(dn, iv);
#pragma unroll
            for (int i = 0; i < 4; i++) {
                const float n  = 1.f - 2.f * iv[i];
                const float ho = sm[OFF_H + j * 36 + r0 + i];
                const float hn = (1.f - zg[i]) * n + zg[i] * ho;
                sm[OFF_H + j * 36 + r0 + i] = hn;
                Af[(r0 + i) * AS2 + 128 + j] = tfsplit(hn);
            }
        }
        __syncthreads();

        // -- G3 (warps 0-12) + next-step nh tiles (warps 13-25) in parallel --
        if (wid < 13) {
            const int n0 = wid * 8;
            float D[8];
#pragma unroll
            for (int i = 0; i < 8; i++) D[i] = 0.f;
            for (int kt = 0; kt < 13; kt++) {
                const int kk = kt * 8;
                float2 F[8];
                ldfrag(F, Af, AS2, g, 128 + kk + cc);
                const float2 b0v = __ldg(&g_W1[(kk + cc) * 104 + n0 + g]);
                const float2 b1v = __ldg(&g_W1[(kk + cc + 4) * 104 + n0 + g]);
                mma3(&D[0], F, b0v, b1v);
                mma3(&D[4], F + 4, b0v, b1v);
            }
            float dv[8], iv[8];
#pragma unroll
            for (int i = 0; i < 8; i++) {
                const int col = n0 + 2 * cc + (i & 1);
                const float bb = (col < 100) ? sm[OFF_BL1 + col] : 0.f;
                const float u = fminf(fmaxf(D[i] + bb, -10.f), 10.f);
                dv[i] = __expf(2.f * u) + 1.f;
            }
            rcp4(dv, iv);
            rcp4(dv + 4, iv + 4);
#pragma unroll
            for (int i = 0; i < 8; i++) {
                const int row = g + (i >> 2) * 16 + ((i >> 1) & 1) * 8;
                const int col = n0 + 2 * cc + (i & 1);
                O1f[row * O1S + col] = tfsplit(1.f - 2.f * iv[i]);
            }
        } else if (t + 1 < T_) {
            nh_tiles();           // writes GX cols 304+ for step t+1
        }
        __syncthreads();

        // -- G4 (tensor): out_t = o1 @ Wl2 + bl2; writes out + YP --
        if (wid < 8) {
            const int n0 = wid * 8;
            float D[8];
#pragma unroll
            for (int i = 0; i < 8; i++) D[i] = 0.f;
            for (int kt = 0; kt < 13; kt++) {
                const int kk = kt * 8;
                float2 F[8];
                ldfrag(F, O1f, O1S, g, kk + cc);
                const float2 b0v = __ldg(&g_W2[(kk + cc) * 64 + n0 + g]);
                const float2 b1v = __ldg(&g_W2[(kk + cc + 4) * 64 + n0 + g]);
                mma3(&D[0], F, b0v, b1v);
                mma3(&D[4], F + 4, b0v, b1v);
            }
#pragma unroll
            for (int i = 0; i < 8; i++) {
                const int row = g + (i >> 2) * 16 + ((i >> 1) & 1) * 8;
                const int col = n0 + 2 * cc + (i & 1);
                const float v = D[i] + sm[OFF_BL2 + col];
                if (row < nr)
                    out[(size_t)(b0 + row) * (YD * T_) + (size_t)col * T_ + t] = v;
                sm[OFF_YP + col * 33 + row] = v;
            }
        }
        __syncthreads();
    }

    // ---- classifier ----
    if (has_cls) {
        float* scr = sm + OFF_GX;
        __syncthreads();
        for (int idx = tid; idx < 32 * CH; idx += NT) {
            const int r = idx & 31, c = idx >> 5;
            float acc = __ldg(&bc1[c]);
            for (int k = 0; k < LAT; k++)
                acc = fmaf(sm[OFF_H + k * 36 + r], __ldg(&Wc1[k * CH + c]), acc);
            scr[c * 36 + r] = fmaxf(acc, 0.f);
        }
        __syncthreads();
        if (tid < nr) {
            float acc = __ldg(&bc2[0]);
            for (int c = 0; c < CH; c++)
                acc = fmaf(scr[c * 36 + tid], __ldg(&Wc2[c]), acc);
            out[(size_t)B_ * YD * T_ + b0 + tid] = fsig(acc);
        }
    }
}

extern "C" void kernel_launch(void* const* d_in, const int* in_sizes, int n_in,
                              void* d_out, int out_size)
{
    cudaFuncSetAttribute(gru_kernel, cudaFuncAttributeMaxDynamicSharedMemorySize,
                         SMEM_FLOATS * (int)sizeof(float));
    prep_kernel<<<128, 256>>>((const float*)d_in[11], (const float*)d_in[13],
                              (const float*)d_in[15], (const float*)d_in[17]);
    const int has_cls = (out_size > B_ * YD * T_) ? 1 : 0;
    gru_kernel<<<NBK, NT, SMEM_FLOATS * sizeof(float)>>>(
        (const float*)d_in[0],   // x
        (const float*)d_in[1],   // y
        d_in[2],                 // y_mask (dtype auto-detected)
        (const float*)d_in[3],  (const float*)d_in[4],   // Wmu1, bmu1
        (const float*)d_in[5],  (const float*)d_in[6],   // Wmu2, bmu2
        (const float*)d_in[12], (const float*)d_in[14],  // bih, bhh
        (const float*)d_in[16], (const float*)d_in[18],  // bl1, bl2
        (const float*)d_in[19], (const float*)d_in[20],  // Wc1, bc1
        (const float*)d_in[21], (const float*)d_in[22],  // Wc2, bc2
        (float*)d_out, has_cls);
}